// round 7
// baseline (speedup 1.0000x reference)
#include <cuda_runtime.h>
#include <cstdint>
#include <cstddef>

// ---------------------------------------------------------------------------
// Problem constants
// ---------------------------------------------------------------------------
#define K_DIM   23232          // FT_IN
#define N_DIM   520            // K_HALF + BUCKETS
#define B_ROWS  4096           // batch
#define M_TOTAL 8192           // 2 * batch (features1 rows then features2 rows)
#define K_HALF  512

// GEMM tiling
#define BM 128
#define BN 128
#define BK 32
#define STAGES 3
#define PADK 36                // smem row stride in floats (36 % 32 == 4 -> conflict-free frags)
#define K_ITERS (K_DIM / BK)   // 726 (exact)

static_assert(K_DIM % BK == 0, "K divisible by BK");

// 17 MB scratch for pre-bias FT activations: rows 0..4095 = A1, 4096..8191 = A2
__device__ float g_act[(size_t)M_TOTAL * N_DIM];

// ---------------------------------------------------------------------------
// helpers
// ---------------------------------------------------------------------------
__device__ __forceinline__ unsigned cvt_tf32(float x) {
    unsigned u;
    asm("cvt.rna.tf32.f32 %0, %1;" : "=r"(u) : "f"(x));
    return u;
}

__device__ __forceinline__ void cp_async16(uint32_t saddr, const void* gptr, int src_bytes) {
    asm volatile("cp.async.cg.shared.global [%0], [%1], 16, %2;\n"
                 :: "r"(saddr), "l"(gptr), "r"(src_bytes) : "memory");
}

__device__ __forceinline__ void cp_commit() {
    asm volatile("cp.async.commit_group;\n" ::: "memory");
}

// ---------------------------------------------------------------------------
// FT GEMM: g_act[m][n] = A[m,:] . ft_w[n,:]   (tf32 mma.sync, fp32 accum)
// A rows 0..4095 from features1, 4096..8191 from features2.
// ---------------------------------------------------------------------------
__global__ __launch_bounds__(256, 2) void ft_gemm_kernel(
    const float* __restrict__ f1,
    const float* __restrict__ f2,
    const float* __restrict__ w)
{
    extern __shared__ float smem[];
    float* sA = smem;                                // [STAGES][BM][PADK]
    float* sB = smem + (size_t)STAGES * BM * PADK;   // [STAGES][BN][PADK]

    const int nt  = blockIdx.x;       // 0..4  (N tiles)
    const int mt  = blockIdx.y;       // 0..63 (M tiles)
    const int tid = threadIdx.x;

    const float* Abase = (mt < 32) ? (f1 + (size_t)mt * BM * K_DIM)
                                   : (f2 + (size_t)(mt - 32) * BM * K_DIM);

    const uint32_t sA_u = (uint32_t)__cvta_generic_to_shared(sA);
    const uint32_t sB_u = (uint32_t)__cvta_generic_to_shared(sB);

    // issue one stage of cp.async loads + commit
    auto load_stage = [&](int st, int it) {
        const int k0 = it * BK;
        #pragma unroll
        for (int i = 0; i < 4; i++) {
            int ch = tid + i * 256;          // 0..1023
            int r  = ch >> 3;                // 0..127
            int c4 = (ch & 7) * 4;           // 0,4,...,28
            uint32_t dst = sA_u + (uint32_t)(((st * BM + r) * PADK + c4) * 4);
            cp_async16(dst, Abase + (size_t)r * K_DIM + k0 + c4, 16);
        }
        #pragma unroll
        for (int i = 0; i < 4; i++) {
            int ch = tid + i * 256;
            int r  = ch >> 3;
            int c4 = (ch & 7) * 4;
            int n  = nt * BN + r;
            const float* src = (n < N_DIM) ? (w + (size_t)n * K_DIM + k0 + c4) : w;
            int sz = (n < N_DIM) ? 16 : 0;   // zero-fill OOB weight rows
            uint32_t dst = sB_u + (uint32_t)(((st * BN + r) * PADK + c4) * 4);
            cp_async16(dst, src, sz);
        }
        cp_commit();
    };

    const int wid  = tid >> 5;
    const int lane = tid & 31;
    const int wm   = (wid & 1) * 64;   // warp M offset   (2 warps in M)
    const int wn   = (wid >> 1) * 32;  // warp N offset   (4 warps in N)
    const int lr   = lane >> 2;        // 0..7
    const int lc   = lane & 3;         // 0..3

    float acc[4][4][4];
    #pragma unroll
    for (int a = 0; a < 4; a++)
        #pragma unroll
        for (int b = 0; b < 4; b++)
            #pragma unroll
            for (int c = 0; c < 4; c++) acc[a][b][c] = 0.f;

    // prologue: STAGES-1 stages in flight
    load_stage(0, 0);
    load_stage(1, 1);

    for (int it = 0; it < K_ITERS; ++it) {
        const int st = it % STAGES;
        asm volatile("cp.async.wait_group 1;\n" ::: "memory");
        __syncthreads();

        const float* A  = sA + (size_t)st * BM * PADK;
        const float* Bs = sB + (size_t)st * BN * PADK;

        #pragma unroll
        for (int ks = 0; ks < 4; ks++) {
            const int kc = ks * 8 + lc;
            unsigned af[4][4], bf[4][2];
            #pragma unroll
            for (int mi = 0; mi < 4; mi++) {
                const int r = wm + mi * 16 + lr;
                af[mi][0] = cvt_tf32(A[r * PADK + kc]);
                af[mi][1] = cvt_tf32(A[(r + 8) * PADK + kc]);
                af[mi][2] = cvt_tf32(A[r * PADK + kc + 4]);
                af[mi][3] = cvt_tf32(A[(r + 8) * PADK + kc + 4]);
            }
            #pragma unroll
            for (int ni = 0; ni < 4; ni++) {
                const int n = wn + ni * 8 + lr;
                bf[ni][0] = cvt_tf32(Bs[n * PADK + kc]);
                bf[ni][1] = cvt_tf32(Bs[n * PADK + kc + 4]);
            }
            #pragma unroll
            for (int mi = 0; mi < 4; mi++)
                #pragma unroll
                for (int ni = 0; ni < 4; ni++)
                    asm("mma.sync.aligned.m16n8k8.row.col.f32.tf32.tf32.f32 "
                        "{%0,%1,%2,%3},{%4,%5,%6,%7},{%8,%9},{%0,%1,%2,%3};"
                        : "+f"(acc[mi][ni][0]), "+f"(acc[mi][ni][1]),
                          "+f"(acc[mi][ni][2]), "+f"(acc[mi][ni][3])
                        : "r"(af[mi][0]), "r"(af[mi][1]), "r"(af[mi][2]), "r"(af[mi][3]),
                          "r"(bf[ni][0]), "r"(bf[ni][1]));
        }
        __syncthreads();
        const int nit = it + (STAGES - 1);
        if (nit < K_ITERS) load_stage(nit % STAGES, nit);
        else               cp_commit();   // keep group accounting uniform
    }

    // epilogue: pre-bias activations to scratch (float2, pairs stay in-bounds: N even)
    #pragma unroll
    for (int mi = 0; mi < 4; mi++) {
        const int r0 = mt * BM + wm + mi * 16 + lr;
        #pragma unroll
        for (int ni = 0; ni < 4; ni++) {
            const int c = nt * BN + wn + ni * 8 + lc * 2;
            if (c < N_DIM) {
                *reinterpret_cast<float2*>(&g_act[(size_t)r0 * N_DIM + c]) =
                    make_float2(acc[mi][ni][0], acc[mi][ni][1]);
                *reinterpret_cast<float2*>(&g_act[(size_t)(r0 + 8) * N_DIM + c]) =
                    make_float2(acc[mi][ni][2], acc[mi][ni][3]);
            }
        }
    }
}

// ---------------------------------------------------------------------------
// Tail: bias + clamp + bucketed h1/h2/out + psqt.   One block per sample.
// ---------------------------------------------------------------------------
__global__ __launch_bounds__(128) void tail_kernel(
    const int*   __restrict__ bucket,
    const float* __restrict__ ft_b,
    const float* __restrict__ h1_w, const float* __restrict__ h1_b,
    const float* __restrict__ h2_w, const float* __restrict__ h2_b,
    const float* __restrict__ out_w, const float* __restrict__ out_b,
    float* __restrict__ out)
{
    __shared__ float ft[1024];
    __shared__ float h1s[16];
    __shared__ float psqt_s;

    const int b   = blockIdx.x;
    const int tid = threadIdx.x;
    const int bk  = bucket[b];

    const float* a1 = g_act + (size_t)b * N_DIM;
    const float* a2 = g_act + (size_t)(B_ROWS + b) * N_DIM;

    for (int i = tid; i < 1024; i += 128) {
        float v = (i < K_HALF) ? (a1[i] + ft_b[i]) : (a2[i - K_HALF] + ft_b[i - K_HALF]);
        ft[i] = fminf(fmaxf(v, 0.f), 1.f);
    }
    if (tid == 0) {
        // ft_b cancels in the difference
        psqt_s = 0.5f * (a1[K_HALF + bk] - a2[K_HALF + bk]);
    }
    __syncthreads();

    const int wid  = tid >> 5;
    const int lane = tid & 31;

    // h1: warp w computes outputs 4w..4w+3 (each a 1024-dot)
    {
        float p0 = 0.f, p1 = 0.f, p2 = 0.f, p3 = 0.f;
        const float* wrow = h1_w + (size_t)(bk * 16 + wid * 4) * 1024;
        for (int i = lane; i < 1024; i += 32) {
            const float x = ft[i];
            p0 += x * wrow[i];
            p1 += x * wrow[1024 + i];
            p2 += x * wrow[2048 + i];
            p3 += x * wrow[3072 + i];
        }
        float p[4] = {p0, p1, p2, p3};
        #pragma unroll
        for (int j = 0; j < 4; j++) {
            float s = p[j];
            #pragma unroll
            for (int o = 16; o; o >>= 1) s += __shfl_down_sync(0xffffffffu, s, o);
            if (lane == 0) {
                s += h1_b[bk * 16 + wid * 4 + j];
                h1s[wid * 4 + j] = fminf(fmaxf(s, 0.f), 1.f);
            }
        }
    }
    __syncthreads();

    // h2 (32 outputs, one per lane of warp 0) -> out
    if (wid == 0) {
        const float* w2 = h2_w + (size_t)(bk * 32 + lane) * 16;
        float s = h2_b[bk * 32 + lane];
        #pragma unroll
        for (int i = 0; i < 16; i++) s += h1s[i] * w2[i];
        s = fminf(fmaxf(s, 0.f), 1.f);
        float v = s * out_w[bk * 32 + lane];
        #pragma unroll
        for (int o = 16; o; o >>= 1) v += __shfl_down_sync(0xffffffffu, v, o);
        if (lane == 0) {
            // FV_SCALE * 2^FT_SHIFT / 2^SHIFT = 16 / 64 = 0.25
            out[b] = v + out_b[bk] + 0.25f * psqt_s;
        }
    }
}

// ---------------------------------------------------------------------------
// launch
// ---------------------------------------------------------------------------
extern "C" void kernel_launch(void* const* d_in, const int* in_sizes, int n_in,
                              void* d_out, int out_size) {
    const int*   bucket = (const int*)  d_in[0];
    const float* f1     = (const float*)d_in[1];
    const float* f2     = (const float*)d_in[2];
    const float* ft_w   = (const float*)d_in[3];
    const float* ft_b   = (const float*)d_in[4];
    const float* h1_w   = (const float*)d_in[5];
    const float* h1_b   = (const float*)d_in[6];
    const float* h2_w   = (const float*)d_in[7];
    const float* h2_b   = (const float*)d_in[8];
    const float* out_w  = (const float*)d_in[9];
    const float* out_b  = (const float*)d_in[10];
    float* out = (float*)d_out;

    constexpr int SMEM_BYTES = STAGES * (BM + BN) * PADK * (int)sizeof(float); // 110592
    cudaFuncSetAttribute(ft_gemm_kernel,
                         cudaFuncAttributeMaxDynamicSharedMemorySize, SMEM_BYTES);

    dim3 grid((N_DIM + BN - 1) / BN, M_TOTAL / BM);   // (5, 64)
    ft_gemm_kernel<<<grid, 256, SMEM_BYTES>>>(f1, f2, ft_w);
    tail_kernel<<<B_ROWS, 128>>>(bucket, ft_b, h1_w, h1_b, h2_w, h2_b,
                                 out_w, out_b, out);
}

// round 14
// speedup vs baseline: 1.3008x; 1.3008x over previous
#include <cuda_runtime.h>
#include <cstdint>
#include <cstddef>

// ---------------------------------------------------------------------------
// Problem constants
// ---------------------------------------------------------------------------
#define K_DIM   23232          // FT_IN
#define N_DIM   520            // K_HALF + BUCKETS
#define B_ROWS  4096
#define K_HALF  512

// GEMM tiling: BM=256 x BN=144, 512 threads (16 warps: 8 in M x 2 in N), occ 1
#define BM      256
#define BN      144
#define N_PAD   576            // 4 * BN  (weight rows padded with zeros)
#define BK      32
#define STAGES  4
#define K_ITERS (K_DIM / BK)   // 726

#define A_BYTES     (BM * 128)            // 32768  (128B per row = 32 tf32)
#define B_BYTES     (BN * 128)            // 18432
#define STAGE_BYTES (A_BYTES + B_BYTES)   // 51200
#define SMEM_TOTAL  (STAGES * STAGE_BYTES)// 204800 (< 227KB, forces occ 1)
#define NCHUNK      ((BM + BN) * 8)       // 3200 16B chunks per stage
#define NPT         7                     // ceil(3200 / 512)

static_assert(K_DIM % BK == 0, "");

// Static scratch (no allocations allowed)
__device__ float g_act[(size_t)2 * B_ROWS * N_DIM];   // pre-bias FT activations
__device__ float g_wr [(size_t)N_PAD * K_DIM];        // rounded+permuted+padded ft_w

// ---------------------------------------------------------------------------
// helpers
// ---------------------------------------------------------------------------
__device__ __forceinline__ unsigned cvt_tf32(float x) {
    unsigned u; asm("cvt.rna.tf32.f32 %0, %1;" : "=r"(u) : "f"(x)); return u;
}
__device__ __forceinline__ void cp_async16(uint32_t saddr, const void* g) {
    asm volatile("cp.async.cg.shared.global [%0], [%1], 16;" :: "r"(saddr), "l"(g) : "memory");
}
__device__ __forceinline__ void cp_commit() {
    asm volatile("cp.async.commit_group;" ::: "memory");
}
__device__ __forceinline__ uint32_t sw128(uint32_t off) {   // SW128 xor swizzle
    return off ^ ((off >> 3) & 0x70);
}

// ---------------------------------------------------------------------------
// Kernel 1: round ft_w to tf32 (rna) and store pair-permuted + zero-padded.
// Within each 8-element k-group, element g goes to position (g&3)*2 + (g>>2),
// so a fragment's (k, k+4) pair becomes adjacent -> one LDS.64, zero cvt in GEMM.
// ---------------------------------------------------------------------------
__global__ __launch_bounds__(256) void preround_w_kernel(const float* __restrict__ w)
{
    const int GROUPS_PER_ROW = K_DIM / 8;                 // 2904
    const size_t TOT = (size_t)N_PAD * GROUPS_PER_ROW;    // 1,672,704
    for (size_t g = (size_t)blockIdx.x * blockDim.x + threadIdx.x; g < TOT;
         g += (size_t)gridDim.x * blockDim.x) {
        const int n   = (int)(g / GROUPS_PER_ROW);
        const int off = (int)(g % GROUPS_PER_ROW) * 8;
        float in[8];
        if (n < N_DIM) {
            const float4* s = (const float4*)(w + (size_t)n * K_DIM + off);
            float4 a = s[0], b = s[1];
            in[0]=a.x; in[1]=a.y; in[2]=a.z; in[3]=a.w;
            in[4]=b.x; in[5]=b.y; in[6]=b.z; in[7]=b.w;
            #pragma unroll
            for (int i = 0; i < 8; i++) in[i] = __uint_as_float(cvt_tf32(in[i]));
        } else {
            #pragma unroll
            for (int i = 0; i < 8; i++) in[i] = 0.f;
        }
        float4* d = (float4*)(g_wr + (size_t)n * K_DIM + off);
        d[0] = make_float4(in[0], in[4], in[1], in[5]);
        d[1] = make_float4(in[2], in[6], in[3], in[7]);
    }
}

// ---------------------------------------------------------------------------
// Kernel 2: FT GEMM, tf32 mma.sync, 256x144 tiles, 4-stage cp.async pipeline.
// grid = (4 N-tiles, 32 M-tiles) = 128 CTAs -> one wave at occ 1.
// ---------------------------------------------------------------------------
__global__ __launch_bounds__(512, 1) void ft_gemm_kernel(
    const float* __restrict__ f1, const float* __restrict__ f2)
{
    extern __shared__ char smem[];
    const uint32_t sb = (uint32_t)__cvta_generic_to_shared(smem);

    const int nt  = blockIdx.x;          // 0..3
    const int mt  = blockIdx.y;          // 0..31
    const int tid = threadIdx.x;

    const float* Abase = (mt < 16) ? (f1 + (size_t)mt * BM * K_DIM)
                                   : (f2 + (size_t)(mt - 16) * BM * K_DIM);
    const int nb = nt * BN;

    // ---- per-thread chunk tables (7 x 16B chunks per thread per stage) ----
    const float* gptr[NPT];
    uint32_t soff[NPT];
    #pragma unroll
    for (int j = 0; j < NPT; j++) {
        int idx = tid + j * 512;
        if (idx < NCHUNK) {
            if (idx < BM * 8) {                       // A chunk (raw features)
                int r = idx >> 3, c = idx & 7;
                soff[j] = sw128((uint32_t)(r * 128 + c * 16));
                gptr[j] = Abase + (size_t)r * K_DIM + c * 4;
            } else {                                  // B chunk (rounded weights)
                int q = idx - BM * 8;
                int r = q >> 3, c = q & 7;
                soff[j] = A_BYTES + sw128((uint32_t)(r * 128 + c * 16));
                gptr[j] = g_wr + (size_t)(nb + r) * K_DIM + c * 4;
            }
        } else { gptr[j] = Abase; soff[j] = 0; }
    }
    const bool act6 = (tid < (NCHUNK - 6 * 512));     // only chunk 6 may be inactive

    auto load_stage = [&](int st) {
        const uint32_t sbase = sb + (uint32_t)st * STAGE_BYTES;
        #pragma unroll
        for (int j = 0; j < 6; j++) cp_async16(sbase + soff[j], gptr[j]);
        if (act6) cp_async16(sbase + soff[6], gptr[6]);
        cp_commit();
        #pragma unroll
        for (int j = 0; j < NPT; j++) gptr[j] += BK;
    };

    // warp layout: 8 warps in M (32 rows each), 2 in N (72 cols each)
    const int wid  = tid >> 5;
    const int lane = tid & 31;
    const int wm   = (wid >> 1) * 32;
    const int wn   = (wid & 1) * 72;
    const int lr   = lane >> 2;          // 0..7
    const int lc   = lane & 3;           // 0..3

    float acc[2][9][4];
    #pragma unroll
    for (int a = 0; a < 2; a++)
        #pragma unroll
        for (int b = 0; b < 9; b++)
            #pragma unroll
            for (int c = 0; c < 4; c++) acc[a][b][c] = 0.f;

    load_stage(0); load_stage(1); load_stage(2);

    for (int it = 0; it < K_ITERS; ++it) {
        const int st = it & 3;
        asm volatile("cp.async.wait_group 2;" ::: "memory");
        __syncthreads();

        const char* As = smem + (size_t)st * STAGE_BYTES;
        const char* Bs = As + A_BYTES;

        #pragma unroll
        for (int ks = 0; ks < 4; ks++) {
            // A fragments: raw floats, swizzled LDS.32 + cvt.rna
            unsigned af[2][4];
            #pragma unroll
            for (int mi = 0; mi < 2; mi++) {
                const int r = wm + mi * 16 + lr;
                const uint32_t c0 = (uint32_t)((ks * 8 + lc) * 4);
                af[mi][0] = cvt_tf32(*(const float*)(As + sw128(r * 128 + c0)));
                af[mi][1] = cvt_tf32(*(const float*)(As + sw128((r + 8) * 128 + c0)));
                af[mi][2] = cvt_tf32(*(const float*)(As + sw128(r * 128 + c0 + 16)));
                af[mi][3] = cvt_tf32(*(const float*)(As + sw128((r + 8) * 128 + c0 + 16)));
            }
            // B fragments: pre-rounded, pair-permuted -> one LDS.64 each, no cvt
            uint2 bf[9];
            #pragma unroll
            for (int ni = 0; ni < 9; ni++) {
                const int n = wn + ni * 8 + lr;
                bf[ni] = *(const uint2*)(Bs + sw128((uint32_t)(n * 128 + ks * 32 + lc * 8)));
            }
            #pragma unroll
            for (int mi = 0; mi < 2; mi++)
                #pragma unroll
                for (int ni = 0; ni < 9; ni++)
                    asm("mma.sync.aligned.m16n8k8.row.col.f32.tf32.tf32.f32 "
                        "{%0,%1,%2,%3},{%4,%5,%6,%7},{%8,%9},{%0,%1,%2,%3};"
                        : "+f"(acc[mi][ni][0]), "+f"(acc[mi][ni][1]),
                          "+f"(acc[mi][ni][2]), "+f"(acc[mi][ni][3])
                        : "r"(af[mi][0]), "r"(af[mi][1]), "r"(af[mi][2]), "r"(af[mi][3]),
                          "r"(bf[ni].x), "r"(bf[ni].y));
        }
        __syncthreads();
        if (it + 3 < K_ITERS) load_stage((it + 3) & 3);
        else                  cp_commit();            // uniform group accounting
    }

    // ---- epilogue: pre-bias activations (float2; N_DIM even, cols even) ----
    #pragma unroll
    for (int mi = 0; mi < 2; mi++) {
        const int r0 = mt * BM + wm + mi * 16 + lr;
        #pragma unroll
        for (int ni = 0; ni < 9; ni++) {
            const int c = nb + wn + ni * 8 + lc * 2;
            if (c < N_DIM) {
                *reinterpret_cast<float2*>(&g_act[(size_t)r0 * N_DIM + c]) =
                    make_float2(acc[mi][ni][0], acc[mi][ni][1]);
                *reinterpret_cast<float2*>(&g_act[(size_t)(r0 + 8) * N_DIM + c]) =
                    make_float2(acc[mi][ni][2], acc[mi][ni][3]);
            }
        }
    }
}

// ---------------------------------------------------------------------------
// Kernel 3: tail — bias + clamp + bucketed h1/h2/out + psqt. One block/sample.
// ---------------------------------------------------------------------------
__global__ __launch_bounds__(128) void tail_kernel(
    const int*   __restrict__ bucket,
    const float* __restrict__ ft_b,
    const float* __restrict__ h1_w, const float* __restrict__ h1_b,
    const float* __restrict__ h2_w, const float* __restrict__ h2_b,
    const float* __restrict__ out_w, const float* __restrict__ out_b,
    float* __restrict__ out)
{
    __shared__ float ft[1024];
    __shared__ float h1s[16];
    __shared__ float psqt_s;

    const int b   = blockIdx.x;
    const int tid = threadIdx.x;
    const int bk  = bucket[b];

    const float* a1 = g_act + (size_t)b * N_DIM;
    const float* a2 = g_act + (size_t)(B_ROWS + b) * N_DIM;

    for (int i = tid; i < 1024; i += 128) {
        float v = (i < K_HALF) ? (a1[i] + ft_b[i]) : (a2[i - K_HALF] + ft_b[i - K_HALF]);
        ft[i] = fminf(fmaxf(v, 0.f), 1.f);
    }
    if (tid == 0) psqt_s = 0.5f * (a1[K_HALF + bk] - a2[K_HALF + bk]);  // ft_b cancels
    __syncthreads();

    const int wid  = tid >> 5;
    const int lane = tid & 31;

    {   // h1: warp w computes outputs 4w..4w+3 (each a 1024-dot)
        float p0 = 0.f, p1 = 0.f, p2 = 0.f, p3 = 0.f;
        const float* wrow = h1_w + (size_t)(bk * 16 + wid * 4) * 1024;
        for (int i = lane; i < 1024; i += 32) {
            const float x = ft[i];
            p0 += x * wrow[i];
            p1 += x * wrow[1024 + i];
            p2 += x * wrow[2048 + i];
            p3 += x * wrow[3072 + i];
        }
        float p[4] = {p0, p1, p2, p3};
        #pragma unroll
        for (int j = 0; j < 4; j++) {
            float s = p[j];
            #pragma unroll
            for (int o = 16; o; o >>= 1) s += __shfl_down_sync(0xffffffffu, s, o);
            if (lane == 0) {
                s += h1_b[bk * 16 + wid * 4 + j];
                h1s[wid * 4 + j] = fminf(fmaxf(s, 0.f), 1.f);
            }
        }
    }
    __syncthreads();

    if (wid == 0) {
        const float* w2 = h2_w + (size_t)(bk * 32 + lane) * 16;
        float s = h2_b[bk * 32 + lane];
        #pragma unroll
        for (int i = 0; i < 16; i++) s += h1s[i] * w2[i];
        s = fminf(fmaxf(s, 0.f), 1.f);
        float v = s * out_w[bk * 32 + lane];
        #pragma unroll
        for (int o = 16; o; o >>= 1) v += __shfl_down_sync(0xffffffffu, v, o);
        if (lane == 0) out[b] = v + out_b[bk] + 0.25f * psqt_s;  // 16*2^0/2^6
    }
}

// ---------------------------------------------------------------------------
// launch
// ---------------------------------------------------------------------------
extern "C" void kernel_launch(void* const* d_in, const int* in_sizes, int n_in,
                              void* d_out, int out_size) {
    const int*   bucket = (const int*)  d_in[0];
    const float* f1     = (const float*)d_in[1];
    const float* f2     = (const float*)d_in[2];
    const float* ft_w   = (const float*)d_in[3];
    const float* ft_b   = (const float*)d_in[4];
    const float* h1_w   = (const float*)d_in[5];
    const float* h1_b   = (const float*)d_in[6];
    const float* h2_w   = (const float*)d_in[7];
    const float* h2_b   = (const float*)d_in[8];
    const float* out_w  = (const float*)d_in[9];
    const float* out_b  = (const float*)d_in[10];
    float* out = (float*)d_out;

    cudaFuncSetAttribute(ft_gemm_kernel,
                         cudaFuncAttributeMaxDynamicSharedMemorySize, SMEM_TOTAL);

    preround_w_kernel<<<2048, 256>>>(ft_w);
    dim3 grid(4, 32);                                  // 128 CTAs: one wave
    ft_gemm_kernel<<<grid, 512, SMEM_TOTAL>>>(f1, f2);
    tail_kernel<<<B_ROWS, 128>>>(bucket, ft_b, h1_w, h1_b, h2_w, h2_b,
                                 out_w, out_b, out);
}

// round 17
// speedup vs baseline: 1.5292x; 1.1756x over previous
#include <cuda_runtime.h>
#include <cuda_fp16.h>
#include <cstdint>
#include <cstddef>

// ---------------------------------------------------------------------------
// Problem constants
// ---------------------------------------------------------------------------
#define K_DIM   23232          // FT_IN
#define N_DIM   520            // K_HALF + BUCKETS
#define B_ROWS  4096
#define M_TOTAL 8192
#define K_HALF  512

// GEMM tiling: BM=256 x BN=144 (fp16), 512 threads (16 warps: 8 M x 2 N), occ 1
#define BM      256
#define BN      144
#define N_PAD   576            // 4 * BN  (weight rows padded with zeros)
#define BK      64             // fp16 -> 128 bytes per smem row
#define K_ITERS (K_DIM / BK)   // 363

#define A_BYTES     (BM * 128)            // 32768
#define B_BYTES     (BN * 128)            // 18432
#define STAGE_BYTES (A_BYTES + B_BYTES)   // 51200
#define STAGES      4
#define SMEM_TOTAL  (STAGES * STAGE_BYTES)// 204800
#define NCHUNK      ((BM + BN) * 8)       // 3200 16B chunks per stage
#define NPT         7                     // ceil(3200 / 512)

static_assert(K_DIM % BK == 0, "");
static_assert(K_DIM % 16 == 0, "");

// Static scratch (no allocations allowed)
__device__ float  g_act[(size_t)M_TOTAL * N_DIM];     // pre-bias FT activations
__device__ __half g_fh [(size_t)M_TOTAL * K_DIM];     // fp16 features (pair-permuted)
__device__ __half g_wh [(size_t)N_PAD  * K_DIM];      // fp16 weights  (pair-permuted, padded)

// ---------------------------------------------------------------------------
// helpers
// ---------------------------------------------------------------------------
__device__ __forceinline__ void cp_async16(uint32_t saddr, const void* g) {
    asm volatile("cp.async.cg.shared.global [%0], [%1], 16;" :: "r"(saddr), "l"(g) : "memory");
}
__device__ __forceinline__ void cp_commit() {
    asm volatile("cp.async.commit_group;" ::: "memory");
}
__device__ __forceinline__ uint32_t sw128(uint32_t off) {   // SW128 xor swizzle
    return off ^ ((off >> 3) & 0x70);
}
__device__ __forceinline__ unsigned h2_bits(half2 h) {      // bit-cast half2 -> u32
    union { half2 h; unsigned u; } c;
    c.h = h;
    return c.u;
}

// Pair-permute one 16-element k-group into fragment-friendly order:
// dest halves = src [0,1, 8,9, 2,3, 10,11, 4,5, 12,13, 6,7, 14,15]
// => an (k, k+1, k+8, k+9) fragment quad is 8 contiguous bytes (one LDS.64).
__device__ __forceinline__ void permute_store16(__half* dst, const float* s) {
    half2 w[8];
    w[0] = __floats2half2_rn(s[0],  s[1]);
    w[1] = __floats2half2_rn(s[8],  s[9]);
    w[2] = __floats2half2_rn(s[2],  s[3]);
    w[3] = __floats2half2_rn(s[10], s[11]);
    w[4] = __floats2half2_rn(s[4],  s[5]);
    w[5] = __floats2half2_rn(s[12], s[13]);
    w[6] = __floats2half2_rn(s[6],  s[7]);
    w[7] = __floats2half2_rn(s[14], s[15]);
    uint4* d = (uint4*)dst;
    d[0] = make_uint4(h2_bits(w[0]), h2_bits(w[1]), h2_bits(w[2]), h2_bits(w[3]));
    d[1] = make_uint4(h2_bits(w[4]), h2_bits(w[5]), h2_bits(w[6]), h2_bits(w[7]));
}

// ---------------------------------------------------------------------------
// Kernel 1a: features -> fp16, pair-permuted.  rows 0..4095 = f1, 4096.. = f2
// ---------------------------------------------------------------------------
__global__ __launch_bounds__(256) void preround_f_kernel(
    const float* __restrict__ f1, const float* __restrict__ f2)
{
    const int GPR = K_DIM / 16;                          // 1452 groups per row
    const size_t TOT = (size_t)M_TOTAL * GPR;
    for (size_t g = (size_t)blockIdx.x * blockDim.x + threadIdx.x; g < TOT;
         g += (size_t)gridDim.x * blockDim.x) {
        const int row = (int)(g / GPR);
        const int off = (int)(g % GPR) * 16;
        const float* src = ((row < B_ROWS) ? (f1 + (size_t)row * K_DIM)
                                           : (f2 + (size_t)(row - B_ROWS) * K_DIM)) + off;
        float s[16];
        const float4* s4 = (const float4*)src;
        float4 a = s4[0], b = s4[1], c = s4[2], d = s4[3];
        s[0]=a.x; s[1]=a.y; s[2]=a.z; s[3]=a.w;
        s[4]=b.x; s[5]=b.y; s[6]=b.z; s[7]=b.w;
        s[8]=c.x; s[9]=c.y; s[10]=c.z; s[11]=c.w;
        s[12]=d.x; s[13]=d.y; s[14]=d.z; s[15]=d.w;
        permute_store16(g_fh + (size_t)row * K_DIM + off, s);
    }
}

// ---------------------------------------------------------------------------
// Kernel 1b: weights -> fp16, pair-permuted, zero-padded to N_PAD rows
// ---------------------------------------------------------------------------
__global__ __launch_bounds__(256) void preround_w_kernel(const float* __restrict__ w)
{
    const int GPR = K_DIM / 16;
    const size_t TOT = (size_t)N_PAD * GPR;
    for (size_t g = (size_t)blockIdx.x * blockDim.x + threadIdx.x; g < TOT;
         g += (size_t)gridDim.x * blockDim.x) {
        const int n   = (int)(g / GPR);
        const int off = (int)(g % GPR) * 16;
        float s[16];
        if (n < N_DIM) {
            const float4* s4 = (const float4*)(w + (size_t)n * K_DIM + off);
            float4 a = s4[0], b = s4[1], c = s4[2], d = s4[3];
            s[0]=a.x; s[1]=a.y; s[2]=a.z; s[3]=a.w;
            s[4]=b.x; s[5]=b.y; s[6]=b.z; s[7]=b.w;
            s[8]=c.x; s[9]=c.y; s[10]=c.z; s[11]=c.w;
            s[12]=d.x; s[13]=d.y; s[14]=d.z; s[15]=d.w;
        } else {
            #pragma unroll
            for (int i = 0; i < 16; i++) s[i] = 0.f;
        }
        permute_store16(g_wh + (size_t)n * K_DIM + off, s);
    }
}

// ---------------------------------------------------------------------------
// Kernel 2: FT GEMM, fp16 mma.sync m16n8k16, 256x144 tiles, 4-stage cp.async.
// grid = (4 N-tiles, 32 M-tiles) = 128 CTAs -> one wave at occ 1.
// ---------------------------------------------------------------------------
__global__ __launch_bounds__(512, 1) void ft_gemm_kernel()
{
    extern __shared__ char smem[];
    const uint32_t sb = (uint32_t)__cvta_generic_to_shared(smem);

    const int nt  = blockIdx.x;          // 0..3
    const int mt  = blockIdx.y;          // 0..31
    const int tid = threadIdx.x;

    const __half* Abase = g_fh + (size_t)mt * BM * K_DIM;
    const int nb = nt * BN;

    // ---- per-thread chunk tables (7 x 16B chunks per thread per stage) ----
    const __half* gptr[NPT];
    uint32_t soff[NPT];
    #pragma unroll
    for (int j = 0; j < NPT; j++) {
        int idx = tid + j * 512;
        if (idx < NCHUNK) {
            if (idx < BM * 8) {                       // A chunk
                int r = idx >> 3, c = idx & 7;
                soff[j] = sw128((uint32_t)(r * 128 + c * 16));
                gptr[j] = Abase + (size_t)r * K_DIM + c * 8;
            } else {                                  // B chunk
                int q = idx - BM * 8;
                int r = q >> 3, c = q & 7;
                soff[j] = A_BYTES + sw128((uint32_t)(r * 128 + c * 16));
                gptr[j] = g_wh + (size_t)(nb + r) * K_DIM + c * 8;
            }
        } else { gptr[j] = Abase; soff[j] = 0; }
    }
    const bool act6 = (tid < (NCHUNK - 6 * 512));     // only chunk 6 may be inactive

    auto load_stage = [&](int st) {
        const uint32_t sbase = sb + (uint32_t)st * STAGE_BYTES;
        #pragma unroll
        for (int j = 0; j < 6; j++) cp_async16(sbase + soff[j], gptr[j]);
        if (act6) cp_async16(sbase + soff[6], gptr[6]);
        cp_commit();
        #pragma unroll
        for (int j = 0; j < NPT; j++) gptr[j] += BK;  // 64 halves = 128 B
    };

    // warp layout: 8 warps in M (32 rows each), 2 in N (72 cols each)
    const int wid  = tid >> 5;
    const int lane = tid & 31;
    const int wm   = (wid >> 1) * 32;
    const int wn   = (wid & 1) * 72;
    const int lr   = lane >> 2;          // 0..7
    const int lc   = lane & 3;           // 0..3

    float acc[2][9][4];
    #pragma unroll
    for (int a = 0; a < 2; a++)
        #pragma unroll
        for (int b = 0; b < 9; b++)
            #pragma unroll
            for (int c = 0; c < 4; c++) acc[a][b][c] = 0.f;

    load_stage(0); load_stage(1); load_stage(2);

    for (int it = 0; it < K_ITERS; ++it) {
        const int st = it & 3;
        asm volatile("cp.async.wait_group 2;" ::: "memory");
        __syncthreads();

        const char* As = smem + (size_t)st * STAGE_BYTES;
        const char* Bs = As + A_BYTES;

        #pragma unroll
        for (int ks = 0; ks < 4; ks++) {              // 4 x K=16 per BK=64
            const uint32_t kb = (uint32_t)(ks * 32 + lc * 8);
            // A fragments: one LDS.64 yields (a0,a2); row+8 yields (a1,a3)
            uint2 alo[2], ahi[2];
            #pragma unroll
            for (int mi = 0; mi < 2; mi++) {
                const int r = wm + mi * 16 + lr;
                alo[mi] = *(const uint2*)(As + sw128((uint32_t)(r * 128) + kb));
                ahi[mi] = *(const uint2*)(As + sw128((uint32_t)((r + 8) * 128) + kb));
            }
            // B fragments: one LDS.64 = (b0,b1)
            uint2 bf[9];
            #pragma unroll
            for (int ni = 0; ni < 9; ni++) {
                const int n = wn + ni * 8 + lr;
                bf[ni] = *(const uint2*)(Bs + sw128((uint32_t)(n * 128) + kb));
            }
            #pragma unroll
            for (int mi = 0; mi < 2; mi++)
                #pragma unroll
                for (int ni = 0; ni < 9; ni++)
                    asm("mma.sync.aligned.m16n8k16.row.col.f32.f16.f16.f32 "
                        "{%0,%1,%2,%3},{%4,%5,%6,%7},{%8,%9},{%0,%1,%2,%3};"
                        : "+f"(acc[mi][ni][0]), "+f"(acc[mi][ni][1]),
                          "+f"(acc[mi][ni][2]), "+f"(acc[mi][ni][3])
                        : "r"(alo[mi].x), "r"(ahi[mi].x), "r"(alo[mi].y), "r"(ahi[mi].y),
                          "r"(bf[ni].x), "r"(bf[ni].y));
        }
        __syncthreads();
        if (it + 3 < K_ITERS) load_stage((it + 3) & 3);
        else                  cp_commit();            // uniform group accounting
    }

    // ---- epilogue: pre-bias activations (float2; N_DIM even, cols even) ----
    #pragma unroll
    for (int mi = 0; mi < 2; mi++) {
        const int r0 = mt * BM + wm + mi * 16 + lr;
        #pragma unroll
        for (int ni = 0; ni < 9; ni++) {
            const int c = nb + wn + ni * 8 + lc * 2;
            if (c < N_DIM) {
                *reinterpret_cast<float2*>(&g_act[(size_t)r0 * N_DIM + c]) =
                    make_float2(acc[mi][ni][0], acc[mi][ni][1]);
                *reinterpret_cast<float2*>(&g_act[(size_t)(r0 + 8) * N_DIM + c]) =
                    make_float2(acc[mi][ni][2], acc[mi][ni][3]);
            }
        }
    }
}

// ---------------------------------------------------------------------------
// Kernel 3: tail — bias + clamp + bucketed h1/h2/out + psqt. One block/sample.
// ---------------------------------------------------------------------------
__global__ __launch_bounds__(128) void tail_kernel(
    const int*   __restrict__ bucket,
    const float* __restrict__ ft_b,
    const float* __restrict__ h1_w, const float* __restrict__ h1_b,
    const float* __restrict__ h2_w, const float* __restrict__ h2_b,
    const float* __restrict__ out_w, const float* __restrict__ out_b,
    float* __restrict__ out)
{
    __shared__ float ft[1024];
    __shared__ float h1s[16];
    __shared__ float psqt_s;

    const int b   = blockIdx.x;
    const int tid = threadIdx.x;
    const int bk  = bucket[b];

    const float* a1 = g_act + (size_t)b * N_DIM;
    const float* a2 = g_act + (size_t)(B_ROWS + b) * N_DIM;

    for (int i = tid; i < 1024; i += 128) {
        float v = (i < K_HALF) ? (a1[i] + ft_b[i]) : (a2[i - K_HALF] + ft_b[i - K_HALF]);
        ft[i] = fminf(fmaxf(v, 0.f), 1.f);
    }
    if (tid == 0) psqt_s = 0.5f * (a1[K_HALF + bk] - a2[K_HALF + bk]);  // ft_b cancels
    __syncthreads();

    const int wid  = tid >> 5;
    const int lane = tid & 31;

    {   // h1: warp w computes outputs 4w..4w+3 (each a 1024-dot)
        float p0 = 0.f, p1 = 0.f, p2 = 0.f, p3 = 0.f;
        const float* wrow = h1_w + (size_t)(bk * 16 + wid * 4) * 1024;
        for (int i = lane; i < 1024; i += 32) {
            const float x = ft[i];
            p0 += x * wrow[i];
            p1 += x * wrow[1024 + i];
            p2 += x * wrow[2048 + i];
            p3 += x * wrow[3072 + i];
        }
        float p[4] = {p0, p1, p2, p3};
        #pragma unroll
        for (int j = 0; j < 4; j++) {
            float s = p[j];
            #pragma unroll
            for (int o = 16; o; o >>= 1) s += __shfl_down_sync(0xffffffffu, s, o);
            if (lane == 0) {
                s += h1_b[bk * 16 + wid * 4 + j];
                h1s[wid * 4 + j] = fminf(fmaxf(s, 0.f), 1.f);
            }
        }
    }
    __syncthreads();

    if (wid == 0) {
        const float* w2 = h2_w + (size_t)(bk * 32 + lane) * 16;
        float s = h2_b[bk * 32 + lane];
        #pragma unroll
        for (int i = 0; i < 16; i++) s += h1s[i] * w2[i];
        s = fminf(fmaxf(s, 0.f), 1.f);
        float v = s * out_w[bk * 32 + lane];
        #pragma unroll
        for (int o = 16; o; o >>= 1) v += __shfl_down_sync(0xffffffffu, v, o);
        if (lane == 0) out[b] = v + out_b[bk] + 0.25f * psqt_s;  // 16*2^0/2^6
    }
}

// ---------------------------------------------------------------------------
// launch
// ---------------------------------------------------------------------------
extern "C" void kernel_launch(void* const* d_in, const int* in_sizes, int n_in,
                              void* d_out, int out_size) {
    const int*   bucket = (const int*)  d_in[0];
    const float* f1     = (const float*)d_in[1];
    const float* f2     = (const float*)d_in[2];
    const float* ft_w   = (const float*)d_in[3];
    const float* ft_b   = (const float*)d_in[4];
    const float* h1_w   = (const float*)d_in[5];
    const float* h1_b   = (const float*)d_in[6];
    const float* h2_w   = (const float*)d_in[7];
    const float* h2_b   = (const float*)d_in[8];
    const float* out_w  = (const float*)d_in[9];
    const float* out_b  = (const float*)d_in[10];
    float* out = (float*)d_out;

    cudaFuncSetAttribute(ft_gemm_kernel,
                         cudaFuncAttributeMaxDynamicSharedMemorySize, SMEM_TOTAL);

    preround_f_kernel<<<4096, 256>>>(f1, f2);
    preround_w_kernel<<<512, 256>>>(ft_w);
    dim3 grid(4, 32);                                  // 128 CTAs: one wave
    ft_gemm_kernel<<<grid, 512, SMEM_TOTAL>>>();
    tail_kernel<<<B_ROWS, 128>>>(bucket, ft_b, h1_w, h1_b, h2_w, h2_b,
                                 out_w, out_b, out);
}